// round 7
// baseline (speedup 1.0000x reference)
#include <cuda_runtime.h>

// FeatureExtractor_50165218017745  (R7: cp.async-staged, register-free pipeline)
// Input : imgs_in [64, 3, 512, 512] float32 in [0,1)
// Output: [64, 96, 4, 4] float32
//
// Loads decoupled from binning: cp.async.cg streams each warp's 48 x 512B
// chunks through a 3-slot smem ring (3 chunks = 1.5 KB in flight per warp,
// ~84 KB/SM) with per-chunk commit groups; consume side is LDS.128 + u16
// parity-packed privatized histograms (bank == lane, conflict-free).
// 16K hist + 12K stage smem, 7 CTAs/SM, 1024 blocks = ONE wave.
// Fused threadfence-reduction epilogue + scratch reset for graph replay.

#define BINS   32
#define BATCH  64
#define PARTS  4
#define NBLK   (BATCH * 4 * PARTS)   // 1024 blocks

__device__ unsigned g_counts[BATCH * 4 * BINS];  // zero-init; reset each run
__device__ unsigned g_done[BATCH];               // zero-init; reset each run

#define CP_ASYNC16(dst_smem, src) \
    asm volatile("cp.async.cg.shared.global [%0], [%1], 16;" \
                 :: "r"(dst_smem), "l"(src) : "memory")
#define CP_COMMIT() asm volatile("cp.async.commit_group;" ::: "memory")
#define CP_WAIT(n)  asm volatile("cp.async.wait_group %0;" :: "n"(n) : "memory")

// bin = floor(32x) for x in [0,1): FFMA.RZ + 2^23 leaves floor(32x) in the
// low mantissa bits (exact for 0 <= 32x < 2^23).
__device__ __forceinline__ unsigned bin_of(float x) {
    return __float_as_uint(__fmaf_rz(x, 32.0f, 8388608.0f)) & 31u;
}

__device__ __forceinline__ void bump4(const float4& a, unsigned short* __restrict__ h) {
    h[bin_of(a.x) << 8] += 1u;
    h[bin_of(a.y) << 8] += 1u;
    h[bin_of(a.z) << 8] += 1u;
    h[bin_of(a.w) << 8] += 1u;
}

// chunk j (0..47): channel c = j>>4, row t = (j>>1)&7, half = j&1
// float4 offset from warp base (compile-time shifts only)
__device__ __forceinline__ int chunk_off(int j) {
    return ((j >> 4) << 16) + (((j >> 1) & 7) << 12) + ((j & 1) << 5);
}

__global__ __launch_bounds__(256, 7)
void fused_kernel(const float* __restrict__ in, float* __restrict__ out) {
    __shared__ unsigned short hist[BINS * 256];   // 16 KB, parity-packed
    __shared__ float4 stage[8][3][32];            // 12 KB: [warp][slot][lane]
    __shared__ unsigned scratch[256 + 1];

    int bid  = blockIdx.x;                  // ((b*4 + q) * PARTS + part)
    int tid  = threadIdx.x;
    int warp = tid >> 5;
    int lane = tid & 31;

    // Warp base pointer (float4 units)
    int part = bid & (PARTS - 1);
    int q    = (bid >> 2) & 3;
    int b    = bid >> 4;
    const float4* gb = (const float4*)in
        + b * 196608 + (q >> 1) * 32768 + (q & 1) * 64
        + (part * 8 + warp) * 128 + lane;

    unsigned sl0 = (unsigned)__cvta_generic_to_shared(&stage[warp][0][lane]);

    // Prologue: 3 chunks in flight BEFORE the zeroing barrier (hides latency).
    CP_ASYNC16(sl0,        gb + chunk_off(0)); CP_COMMIT();
    CP_ASYNC16(sl0 + 512,  gb + chunk_off(1)); CP_COMMIT();
    CP_ASYNC16(sl0 + 1024, gb + chunk_off(2)); CP_COMMIT();

    // zero private histograms (4096 u32 words / 256 threads)
    {
        uint4* z = (uint4*)hist;
        #pragma unroll
        for (int i = 0; i < 4; i++)
            z[tid + 256 * i] = make_uint4(0u, 0u, 0u, 0u);
    }
    __syncthreads();

    // Parity-packed slot: byte = bin*512 + (warp>>1)*128 + lane*4 + (warp&1)*2
    // -> bank = lane for every bin.
    unsigned short* h = hist + ((warp >> 1) << 6) + (lane << 1) + (warp & 1);

    // Main: consume chunk k (slot k%3), refill with chunk k+3 into same slot.
    #pragma unroll 1
    for (int k = 0; k < 45; k += 3) {
        CP_WAIT(2);
        {
            float4 v = stage[warp][0][lane];
            CP_ASYNC16(sl0, gb + chunk_off(k + 3)); CP_COMMIT();
            bump4(v, h);
        }
        CP_WAIT(2);
        {
            float4 v = stage[warp][1][lane];
            CP_ASYNC16(sl0 + 512, gb + chunk_off(k + 4)); CP_COMMIT();
            bump4(v, h);
        }
        CP_WAIT(2);
        {
            float4 v = stage[warp][2][lane];
            CP_ASYNC16(sl0 + 1024, gb + chunk_off(k + 5)); CP_COMMIT();
            bump4(v, h);
        }
    }
    // Tail: chunks 45, 46, 47
    CP_WAIT(2); { float4 v = stage[warp][0][lane]; bump4(v, h); }
    CP_WAIT(1); { float4 v = stage[warp][1][lane]; bump4(v, h); }
    CP_WAIT(0); { float4 v = stage[warp][2][lane]; bump4(v, h); }

    __syncthreads();

    // Block reduction: 8192 u16 counters -> 32 bin sums (rotated reads).
    unsigned s = 0;
    int base = (tid & 31) * 256 + (tid >> 5) * 32;
    #pragma unroll
    for (int i = 0; i < 32; i++)
        s += hist[base + ((i + tid) & 31)];
    scratch[tid] = s;
    __syncthreads();
    if (tid < 32) {
        unsigned tot = 0;
        #pragma unroll
        for (int c = 0; c < 8; c++)
            tot += scratch[tid + 32 * c];
        atomicAdd(&g_counts[((b << 2) + q) * BINS + tid], tot);
    }

    // Release counts, then bump per-batch arrival counter.
    __threadfence();
    __syncthreads();
    if (tid == 0)
        scratch[256] = atomicAdd(&g_done[b], 1u);
    __syncthreads();
    unsigned rank = scratch[256];
    if (rank != 4 * PARTS - 1) return;      // not the last block of batch b

    // ---- last block of batch b: finalize (overlapped with other batches) ----
    __threadfence();                        // acquire
    __syncthreads();

    float* s1  = (float*)hist;              // [128]: per-quadrant hist / 65536
    float* s0v = ((float*)hist) + 128;      // [32] : full-image hist / 262144

    if (tid < 128) {
        unsigned c = __ldcg(&g_counts[(b << 7) + tid]);
        s1[tid] = (float)c * (1.0f / 65536.0f);
        g_counts[(b << 7) + tid] = 0u;      // reset for next replay
    }
    __syncthreads();
    if (tid < 32)
        s0v[tid] = (s1[tid] + s1[32 + tid] + s1[64 + tid] + s1[96 + tid]) * 0.25f;
    if (tid == 0)
        g_done[b] = 0u;                     // reset for next replay
    __syncthreads();

    #pragma unroll
    for (int k = 0; k < 6; k++) {
        int idx  = tid + 256 * k;           // 0..1535
        int ch   = idx >> 4;
        int cell = idx & 15;                // y*4 + x
        float v = 0.0f;
        if (ch < 32) {
            v = s0v[ch];
        } else if (ch < 64) {
            int qq = ((cell >> 3) << 1) | ((cell >> 1) & 1);  // (y>>1)*2+(x>>1)
            v = s1[qq * BINS + (ch - 32)];
        }
        out[b * 1536 + idx] = v;
    }
}

extern "C" void kernel_launch(void* const* d_in, const int* in_sizes, int n_in,
                              void* d_out, int out_size) {
    (void)in_sizes; (void)n_in; (void)out_size;
    fused_kernel<<<NBLK, 256>>>((const float*)d_in[0], (float*)d_out);
}

// round 8
// speedup vs baseline: 1.0468x; 1.0468x over previous
#include <cuda_runtime.h>

// FeatureExtractor_50165218017745  (R8: full-row streaming, u8 dual-q hist)
// Input : imgs_in [64, 3, 512, 512] float32 in [0,1)
// Output: [64, 96, 4, 4] float32
//
// Each warp streams FULL 2KB image rows contiguously (perfect DRAM row-buffer
// locality) and bins the left/right halves into two per-thread u8 histograms
// packed into one 16KB array: u8 = bin*512 + (warp>>1)*128 + lane*4 +
// (warp&1)*2 + qx  -> bank == lane, conflict-free, per-thread-exclusive.
// Max count/thread/q = 96 < 255. Blocks = (b, qy, part) = 1024, 7 CTA/SM,
// one wave. dp4a byte-masked reduction; fused finalize + replay reset.

#define BINS   32
#define BATCH  64
#define NBLK   1024   // 64 b * 2 qy * 8 part

__device__ unsigned g_counts[BATCH * 4 * BINS];  // zero-init; reset each run
__device__ unsigned g_done[BATCH];               // zero-init; reset each run

// bin = floor(32x) for x in [0,1): FFMA.RZ + 2^23 leaves floor(32x) in the
// low mantissa bits (exact for 0 <= 32x < 2^23).
__device__ __forceinline__ unsigned bin_of(float x) {
    return __float_as_uint(__fmaf_rz(x, 32.0f, 8388608.0f)) & 31u;
}

__device__ __forceinline__ void bump4(const float4& a, unsigned char* __restrict__ h) {
    h[bin_of(a.x) << 9] += 1u;
    h[bin_of(a.y) << 9] += 1u;
    h[bin_of(a.z) << 9] += 1u;
    h[bin_of(a.w) << 9] += 1u;
}

// half-row pointer: bb = in + b*196608 + qy*32768 (float4 units);
// ridx in [0,768): c = ridx>>8, r = ridx&255; half selects 1KB half of row.
__device__ __forceinline__ const float4* half_ptr(const float4* bb, int ridx,
                                                  int half, int lane) {
    return bb + ((ridx >> 8) << 16) + ((ridx & 255) << 7) + (half << 6) + lane;
}

__global__ __launch_bounds__(256, 7)
void fused_kernel(const float* __restrict__ in, float* __restrict__ out) {
    __shared__ unsigned char hist8[BINS * 512];   // 16 KB
    __shared__ unsigned scratch[512 + 1];

    int bid  = blockIdx.x;                  // ((b*2 + qy)*8 + part)
    int part = bid & 7;
    int qy   = (bid >> 3) & 1;
    int b    = bid >> 4;

    int tid  = threadIdx.x;
    int warp = tid >> 5;
    int lane = tid & 31;

    // zero histograms (4096 words / 256 threads = 4 uint4 each)
    {
        uint4* z = (uint4*)hist8;
        #pragma unroll
        for (int i = 0; i < 4; i++)
            z[tid + 256 * i] = make_uint4(0u, 0u, 0u, 0u);
    }
    __syncthreads();

    unsigned char* h0 = hist8 + ((warp >> 1) << 7) + (lane << 2) + ((warp & 1) << 1);
    unsigned char* h1 = h0 + 1;

    // Warp streams 12 consecutive full rows (24 half-rows, alternating q).
    {
        const float4* bb = (const float4*)in + b * 196608 + qy * 32768;
        int r0 = part * 96 + warp * 12;

        const float4* p = half_ptr(bb, r0, 0, lane);
        float4 x0 = p[0], x1 = p[32];          // hr=0 (q0)
        p = half_ptr(bb, r0, 1, lane);
        float4 y0 = p[0], y1 = p[32];          // hr=1 (q1)

        #pragma unroll
        for (int hr = 0; hr < 24; hr++) {
            float4 z0, z1;
            if (hr < 22) {                     // prefetch hr+2 (same q parity)
                const float4* pz = half_ptr(bb, r0 + (hr >> 1) + 1, hr & 1, lane);
                z0 = pz[0]; z1 = pz[32];
            }
            unsigned char* hq = (hr & 1) ? h1 : h0;
            bump4(x0, hq);
            bump4(x1, hq);
            x0 = y0; x1 = y1;
            y0 = z0; y1 = z1;
        }
    }
    __syncthreads();

    // Reduction: word w of bin contains bytes (wp0,q0),(wp0,q1),(wp1,q0),(wp1,q1).
    // dp4a masks split q0/q1. Rotated reads to spread banks.
    {
        unsigned acc0 = 0, acc1 = 0;
        int bin = tid & 31, grp = tid >> 5;
        const unsigned* hw = (const unsigned*)hist8;
        int base = bin * 128 + grp * 16;
        #pragma unroll
        for (int i = 0; i < 16; i++) {
            unsigned w = hw[base + ((i + bin) & 15)];
            acc0 = __dp4a(w, 0x00010001u, acc0);   // bytes 0,2 -> q0
            acc1 = __dp4a(w, 0x01000100u, acc1);   // bytes 1,3 -> q1
        }
        scratch[tid] = acc0;
        scratch[256 + tid] = acc1;
    }
    __syncthreads();
    if (tid < 64) {
        int q = tid >> 5, bn = tid & 31;
        unsigned tot = 0;
        #pragma unroll
        for (int c = 0; c < 8; c++)
            tot += scratch[q * 256 + c * 32 + bn];
        atomicAdd(&g_counts[((b << 2) + (qy << 1) + q) * BINS + bn], tot);
    }

    // Release counts, then bump per-batch arrival counter (16 blocks/batch).
    __threadfence();
    __syncthreads();
    if (tid == 0)
        scratch[512] = atomicAdd(&g_done[b], 1u);
    __syncthreads();
    unsigned rank = scratch[512];
    if (rank != 15u) return;                // not the last block of batch b

    // ---- last block of batch b: finalize (overlapped with other batches) ----
    __threadfence();                        // acquire
    __syncthreads();

    float* s1  = (float*)hist8;             // [128]: per-quadrant hist / 65536
    float* s0v = ((float*)hist8) + 128;     // [32] : full-image hist / 262144

    if (tid < 128) {
        unsigned c = __ldcg(&g_counts[(b << 7) + tid]);
        s1[tid] = (float)c * (1.0f / 65536.0f);
        g_counts[(b << 7) + tid] = 0u;      // reset for next replay
    }
    __syncthreads();
    if (tid < 32)
        s0v[tid] = (s1[tid] + s1[32 + tid] + s1[64 + tid] + s1[96 + tid]) * 0.25f;
    if (tid == 0)
        g_done[b] = 0u;                     // reset for next replay
    __syncthreads();

    #pragma unroll
    for (int k = 0; k < 6; k++) {
        int idx  = tid + 256 * k;           // 0..1535
        int ch   = idx >> 4;
        int cell = idx & 15;                // y*4 + x
        float v = 0.0f;
        if (ch < 32) {
            v = s0v[ch];
        } else if (ch < 64) {
            int qq = ((cell >> 3) << 1) | ((cell >> 1) & 1);  // (y>>1)*2+(x>>1)
            v = s1[qq * BINS + (ch - 32)];
        }
        out[b * 1536 + idx] = v;
    }
}

extern "C" void kernel_launch(void* const* d_in, const int* in_sizes, int n_in,
                              void* d_out, int out_size) {
    (void)in_sizes; (void)n_in; (void)out_size;
    fused_kernel<<<NBLK, 256>>>((const float*)d_in[0], (float*)d_out);
}